// round 16
// baseline (speedup 1.0000x reference)
#include <cuda_runtime.h>
#include <cuda_fp16.h>
#include <math.h>
#include <stdint.h>

// Problem constants
#define BATCH  128
#define SEQ    197
#define DMODEL 768
#define NQKV   2304                // 3 * DMODEL (packed Q,K,V)
#define NFUSE  2432                // NQKV + 128 (h1 cols 2304..2367, pad ..2431)
#define NHEAD  12
#define DHEAD  64
#define M_TOT  (BATCH * SEQ)       // 25216 = 197 * 128
#define SPAD   224                 // padded key count (7 x 32)

// -------------------- scratch (__device__ globals; no allocs allowed) ------
__device__ unsigned char g_mask[M_TOT];
__device__ float g_bfuse[NFUSE];

// fp16 operands (single-pass fp16; fp32 accumulate in MMA)
__device__ __half g_hh[M_TOT * DMODEL];                        // hidden
__device__ __half g_ch[M_TOT * DMODEL], g_cl[M_TOT * DMODEL];  // ctx hi/lo
__device__ __half g_qkvh[(size_t)M_TOT * NQKV];                // packed Q,K (V region unused)
// V transposed: [(b*12+h)*64 + d][224 keys], zero-init padding keys>=197
__device__ __half g_vt[(size_t)BATCH * NHEAD * DHEAD * SPAD];

// packed [Wqkv | W1pad]^T [2432, 768] ; Wd^T
__device__ __half g_wfuse[(size_t)NFUSE * DMODEL];
__device__ __half g_wdh[DMODEL * DMODEL];

// ======================= warp MMA helpers (arch-neutral PTX) ===============
__device__ __forceinline__ uint32_t smem_u32(const void* p) {
    uint32_t a;
    asm("{ .reg .u64 t; cvta.to.shared.u64 t, %1; cvt.u32.u64 %0, t; }"
        : "=r"(a) : "l"(p));
    return a;
}

__device__ __forceinline__ void ldsm_x4(uint32_t r[4], uint32_t addr) {
    asm volatile("ldmatrix.sync.aligned.m8n8.x4.shared.b16 {%0,%1,%2,%3}, [%4];"
                 : "=r"(r[0]), "=r"(r[1]), "=r"(r[2]), "=r"(r[3]) : "r"(addr));
}

__device__ __forceinline__ void mma_16816(float d[4],
                                          const uint32_t a[4],
                                          const uint32_t b0, const uint32_t b1) {
    asm volatile(
        "mma.sync.aligned.m16n8k16.row.col.f32.f16.f16.f32 "
        "{%0,%1,%2,%3}, {%4,%5,%6,%7}, {%8,%9}, {%0,%1,%2,%3};"
        : "+f"(d[0]), "+f"(d[1]), "+f"(d[2]), "+f"(d[3])
        : "r"(a[0]), "r"(a[1]), "r"(a[2]), "r"(a[3]), "r"(b0), "r"(b1));
}

__device__ __forceinline__ void cp16(uint32_t saddr, const void* g) {
    asm volatile("cp.async.cg.shared.global [%0], [%1], 16;"
                 :: "r"(saddr), "l"(g) : "memory");
}

// ===========================================================================
// fp16 single-pass GEMM, BK=64, 3-stage cp.async, ONE barrier per k-chunk.
// 128 threads, 4 warps in 2x2, warp tile 64x64 (LDSM:MMA ratio 4.0).
// EPI 2: mask ? acc+bias+(resid hi+lo) : fallback -> fp32
// EPI 3: col<1536      -> fp16 packed Q/K (ld NQKV)
//        col<NQKV      -> fp16 V transposed into Vt[(b,h),d,s]
//        col<NQKV+64   -> h1 = relu(acc+bias); fused mask dot with W2
//        else          -> discard (zero pad)
// ===========================================================================
#define GSROW 72   // smem row pitch in halves (144 B = 9 x 16B, odd -> conflict-free)
#define GBN  128
#define GSTAGE ((128 + GBN) * GSROW)   // halves per stage: 18432

__device__ __forceinline__ void stage_load(
    __half* st, int tid, int bm, int bn, int k0,
    const __half* A, const __half* B)
{
    __half* pA = st;
    __half* pB = st + 128 * GSROW;
#pragma unroll
    for (int i = 0; i < 8; i++) {
        int idx = tid + i * 128;
        int r = idx >> 3, c = idx & 7;
        const size_t go = (size_t)(bm + r) * DMODEL + k0 + c * 8;
        cp16(smem_u32(&pA[r * GSROW + c * 8]), A + go);
    }
#pragma unroll
    for (int i = 0; i < 8; i++) {
        int idx = tid + i * 128;
        int r = idx >> 3, c = idx & 7;
        const size_t go = (size_t)(bn + r) * DMODEL + k0 + c * 8;
        cp16(smem_u32(&pB[r * GSROW + c * 8]), B + go);
    }
    asm volatile("cp.async.commit_group;" ::: "memory");
}

template <int EPI>
__global__ __launch_bounds__(128, 2) void mma_gemm(
    const __half* __restrict__ A, const __half* __restrict__ B,
    const float* __restrict__ bias, float* __restrict__ C, int ldo,
    const unsigned char* __restrict__ mask,
    const float* __restrict__ fallback,
    __half* __restrict__ Chh, __half* __restrict__ Vt,
    const __half* __restrict__ Rh, const __half* __restrict__ Rl,
    const float* __restrict__ W2, const float* __restrict__ b2)
{
    extern __shared__ __half dynsmem[];

    const int tid  = threadIdx.x;
    const int wid  = tid >> 5;
    const int lane = tid & 31;
    const int wm   = wid & 1;          // 2 warps along M (64 rows each)
    const int wn   = wid >> 1;         // 2 warps along N (64 cols each)
    const int bm   = blockIdx.y * 128;
    const int bn   = blockIdx.x * GBN;

    float acc[4][8][4];
#pragma unroll
    for (int mt = 0; mt < 4; mt++)
#pragma unroll
        for (int nt = 0; nt < 8; nt++)
#pragma unroll
            for (int e = 0; e < 4; e++) acc[mt][nt][e] = 0.0f;

    const int a_row  = (lane & 15);
    const int a_koff = (lane >> 4) * 8;
    const int b_rowl = ((lane >> 4) & 1) * 8 + (lane & 7);
    const int b_koff = ((lane >> 3) & 1) * 8;

    const uint32_t smbase = smem_u32(dynsmem);

    stage_load(dynsmem,          tid, bm, bn,  0, A, B);
    stage_load(dynsmem + GSTAGE, tid, bm, bn, 64, A, B);

    for (int kc = 0; kc < 12; kc++) {
        if (kc < 11) {
            asm volatile("cp.async.wait_group 1;" ::: "memory");
        } else {
            asm volatile("cp.async.wait_group 0;" ::: "memory");
        }
        __syncthreads();
        if (kc < 10) {
            stage_load(dynsmem + ((kc + 2) % 3) * GSTAGE, tid, bm, bn,
                       (kc + 2) * 64, A, B);
        }

        const uint32_t sA = smbase + (uint32_t)((kc % 3) * GSTAGE) * 2u;
        const uint32_t sB = sA + 128 * GSROW * 2u;

        // ---- 16-step flat pipeline, double-buffered fragments ----
        uint32_t aa[2][4][4];   // [ks parity][mt]
        uint32_t bb[2][4];      // [step parity]

#pragma unroll
        for (int mt = 0; mt < 4; mt++)
            ldsm_x4(aa[0][mt],
                    sA + (uint32_t)((wm * 64 + mt * 16 + a_row) * GSROW + a_koff) * 2u);
        ldsm_x4(bb[0],
                sB + (uint32_t)((wn * 64 + b_rowl) * GSROW + b_koff) * 2u);

#pragma unroll
        for (int step = 0; step < 16; step++) {
            const int ks  = step >> 2;
            const int np  = step & 3;
            const int cur = step & 1;
            if (step < 15) {
                const int nks = (step + 1) >> 2;
                const int nnp = (step + 1) & 3;
                ldsm_x4(bb[cur ^ 1],
                        sB + (uint32_t)((wn * 64 + nnp * 16 + b_rowl) * GSROW
                                        + nks * 16 + b_koff) * 2u);
                if (nnp == 0) {
#pragma unroll
                    for (int mt = 0; mt < 4; mt++)
                        ldsm_x4(aa[nks & 1][mt],
                                sA + (uint32_t)((wm * 64 + mt * 16 + a_row) * GSROW
                                                + nks * 16 + a_koff) * 2u);
                }
            }
#pragma unroll
            for (int h = 0; h < 2; h++) {
                const int nt = 2 * np + h;
#pragma unroll
                for (int mt = 0; mt < 4; mt++)
                    mma_16816(acc[mt][nt], aa[ks & 1][mt],
                              bb[cur][2 * h], bb[cur][2 * h + 1]);
            }
        }
    }

    // ---- epilogue ----
    const int g  = lane >> 2;
    const int cc = (lane & 3) * 2;
#pragma unroll
    for (int mt = 0; mt < 4; mt++) {
#pragma unroll
        for (int half = 0; half < 2; half++) {
            const int row = bm + wm * 64 + mt * 16 + g + half * 8;
            const bool mk = (EPI == 2) ? (mask[row] != 0) : false;
            const int bb2 = row / SEQ;             // used by EPI 3 V path
            const int ss = row - bb2 * SEQ;
            float mdot = 0.0f;                      // fused mask dot (EPI 3)
#pragma unroll
            for (int nt = 0; nt < 8; nt++) {
                const int col = bn + wn * 64 + nt * 8 + cc;
                float o0 = acc[mt][nt][2 * half + 0] + bias[col];
                float o1 = acc[mt][nt][2 * half + 1] + bias[col + 1];
                if (EPI == 3) {
                    if (col < 1536) {
                        const size_t go = (size_t)row * NQKV + col;
                        __half hv[2] = {__float2half_rn(o0), __float2half_rn(o1)};
                        *(uint32_t*)(Chh + go) = *(uint32_t*)hv;
                    } else if (col < NQKV) {
                        const int which = col - 1536;
                        const int hh = which >> 6;
                        const int d  = which & 63;
                        __half* vp = Vt + ((size_t)(bb2 * NHEAD + hh) * DHEAD + d)
                                          * SPAD + ss;
                        vp[0]    = __float2half_rn(o0);
                        vp[SPAD] = __float2half_rn(o1);   // d+1 row
                    } else if (col < NQKV + 64) {
                        const int hcol = col - NQKV;
                        mdot += fmaxf(o0, 0.0f) * W2[hcol]
                              + fmaxf(o1, 0.0f) * W2[hcol + 1];
                    }
                } else {  // EPI == 2
                    const size_t go = (size_t)row * ldo + col;
                    float* cp = C + go;
                    if (mk) {
                        float r0f = __half2float(Rh[go]) + __half2float(Rl[go]);
                        float r1f = __half2float(Rh[go + 1]) + __half2float(Rl[go + 1]);
                        *(float2*)cp = make_float2(o0 + r0f, o1 + r1f);
                    } else {
                        const float* fb = fallback + go;
                        *(float2*)cp = make_float2(fb[0], fb[1]);
                    }
                }
            }
            if (EPI == 3 && (bn + wn * 64) == NQKV) {
                // quad reduction: lanes {x, x^1, x^2, x^3} share this row
                mdot += __shfl_xor_sync(0xffffffffu, mdot, 1);
                mdot += __shfl_xor_sync(0xffffffffu, mdot, 2);
                if ((lane & 3) == 0) {
                    float p = 1.0f / (1.0f + __expf(-(mdot + b2[0])));
                    g_mask[row] = (unsigned char)((ss == 0) || (p >= 0.05f));
                }
            }
        }
    }
}

// ===========================================================================
// ONE prep kernel: half_convert | transpose_qkv | transpose W1 | w1 pad |
//                  transpose Wd | pack bias   (blockIdx.x range dispatch)
// ===========================================================================
#define NB_HC   (M_TOT * DMODEL / 4 / 256)   // 18912
#define NB_TQKV 1728
#define NB_TW1  48
#define NB_PAD  24
#define NB_TWD  576
#define NB_BIAS 10
#define NB_PREP (NB_HC + NB_TQKV + NB_TW1 + NB_PAD + NB_TWD + NB_BIAS)

__global__ __launch_bounds__(256) void prep_kernel(
    const float* __restrict__ hidden,
    const float* __restrict__ Wq, const float* __restrict__ Wk,
    const float* __restrict__ Wv, const float* __restrict__ Wd,
    const float* __restrict__ W1,
    const float* __restrict__ bq, const float* __restrict__ bk,
    const float* __restrict__ bv, const float* __restrict__ b1)
{
    __shared__ float t[32][33];
    const int tid = threadIdx.x;
    int bid = blockIdx.x;

    if (bid < NB_HC) {
        int i = bid * 256 + tid;
        float4 x = *(const float4*)(hidden + (size_t)i * 4);
        __half hv[4] = {__float2half_rn(x.x), __float2half_rn(x.y),
                        __float2half_rn(x.z), __float2half_rn(x.w)};
        *(uint2*)(g_hh + (size_t)i * 4) = *(uint2*)hv;
        return;
    }
    bid -= NB_HC;
    if (bid < NB_TQKV) {
        const int k0 = (bid % 24) * 32;
        const int yy = bid / 24;
        const int which = yy / 24;
        const int n0 = (yy % 24) * 32;
        const float* W = (which == 0) ? Wq : (which == 1) ? Wk : Wv;
        const int tx = tid & 31, ty = tid >> 5;
#pragma unroll
        for (int i = 0; i < 32; i += 8)
            t[ty + i][tx] = W[(size_t)(k0 + ty + i) * DMODEL + n0 + tx];
        __syncthreads();
#pragma unroll
        for (int i = 0; i < 32; i += 8)
            g_wfuse[(size_t)(which * DMODEL + n0 + ty + i) * DMODEL + k0 + tx] =
                __float2half_rn(t[tx][ty + i]);
        return;
    }
    bid -= NB_TQKV;
    if (bid < NB_TW1) {
        const int k0 = (bid % 24) * 32;
        const int n0 = (bid / 24) * 32;
        const int tx = tid & 31, ty = tid >> 5;
#pragma unroll
        for (int i = 0; i < 32; i += 8)
            t[ty + i][tx] = W1[(size_t)(k0 + ty + i) * 64 + n0 + tx];
        __syncthreads();
#pragma unroll
        for (int i = 0; i < 32; i += 8)
            g_wfuse[(size_t)(NQKV + n0 + ty + i) * DMODEL + k0 + tx] =
                __float2half_rn(t[tx][ty + i]);
        return;
    }
    bid -= NB_TW1;
    if (bid < NB_PAD) {
        int i = bid * 256 + tid;
        if (i < 6144)
            ((uint4*)(g_wfuse + (size_t)(NQKV + 64) * DMODEL))[i] =
                make_uint4(0, 0, 0, 0);
        return;
    }
    bid -= NB_PAD;
    if (bid < NB_TWD) {
        const int k0 = (bid % 24) * 32;
        const int n0 = (bid / 24) * 32;
        const int tx = tid & 31, ty = tid >> 5;
#pragma unroll
        for (int i = 0; i < 32; i += 8)
            t[ty + i][tx] = Wd[(size_t)(k0 + ty + i) * DMODEL + n0 + tx];
        __syncthreads();
#pragma unroll
        for (int i = 0; i < 32; i += 8)
            g_wdh[(size_t)(n0 + ty + i) * DMODEL + k0 + tx] =
                __float2half_rn(t[tx][ty + i]);
        return;
    }
    bid -= NB_TWD;
    {
        int i = bid * 256 + tid;
        if (i < NFUSE) {
            float v;
            if      (i < 768)  v = bq[i];
            else if (i < 1536) v = bk[i - 768];
            else if (i < 2304) v = bv[i - 1536];
            else if (i < 2368) v = b1[i - 2304];
            else               v = 0.0f;
            g_bfuse[i] = v;
        }
    }
}

// ===========================================================================
// MMA attention: one CTA per (b, h). V staged from pre-transposed g_vt.
// ===========================================================================
#define KP   72      // K/Q smem pitch (halves)
#define VP   232     // Vt / P pitch (halves)
#define PFP  228     // P fp32 pitch (floats)

#define OFF_KH  0
#define OFF_VTH (OFF_KH + 232 * KP * 2)          // 33408
#define OFF_QH  (OFF_VTH + 64 * VP * 2)          // 63104
#define OFF_PF  (OFF_QH + 32 * KP * 2)           // 67712
#define OFF_PBH (OFF_PF + 32 * PFP * 4)          // 96896
#define ATT_SMEM (OFF_PBH + 32 * VP * 2)         // 111744

__global__ __launch_bounds__(256, 2) void attn_mma()
{
    extern __shared__ char sm[];
    __half* sKh  = (__half*)(sm + OFF_KH);
    __half* sVth = (__half*)(sm + OFF_VTH);
    __half* sQh  = (__half*)(sm + OFF_QH);
    float*  sPf  = (float*)(sm + OFF_PF);
    __half* sPbh = (__half*)(sm + OFF_PBH);

    const int b   = blockIdx.x / NHEAD;
    const int h   = blockIdx.x % NHEAD;
    const int tid = threadIdx.x;
    const int wid = tid >> 5;
    const int lane = tid & 31;
    const int rbase = b * SEQ;

    const size_t qoff = (size_t)h * DHEAD;
    const size_t koff = (size_t)DMODEL + h * DHEAD;
    const int hc = h * DHEAD;
    const __half* vt = g_vt + (size_t)(b * NHEAD + h) * DHEAD * SPAD;

    const int a_row  = (lane & 15);
    const int a_koff = (lane >> 4) * 8;
    const int b_rowl = ((lane >> 4) & 1) * 8 + (lane & 7);
    const int b_koff = ((lane >> 3) & 1) * 8;
    const int g  = lane >> 2;
    const int cc = (lane & 3) * 2;

    // ---- stage K (zero-padded rows) ----
    {
        const uint4 z = make_uint4(0, 0, 0, 0);
        for (int idx = tid; idx < SPAD * 8; idx += 256) {
            int r = idx >> 3, c8 = (idx & 7) * 8;
            uint4 vh = z;
            if (r < SEQ) {
                const size_t go = (size_t)(rbase + r) * NQKV + koff + c8;
                vh = *(const uint4*)&g_qkvh[go];
            }
            *(uint4*)&sKh[r * KP + c8] = vh;
        }
    }
    // ---- stage V transposed (uint4 from pre-transposed g_vt) ----
    {
        for (int idx = tid; idx < 64 * 28; idx += 256) {   // 1792 uint4
            int d = idx / 28, k8 = (idx % 28) * 8;
            *(uint4*)&sVth[d * VP + k8] = *(const uint4*)&vt[d * SPAD + k8];
        }
    }
    // ---- stage Q tile 0 ----
    {
        int r = tid >> 3, c8 = (tid & 7) * 8;
        uint4 vh = make_uint4(0, 0, 0, 0);
        if (r < SEQ) {
            const size_t go = (size_t)(rbase + r) * NQKV + qoff + c8;
            vh = *(const uint4*)&g_qkvh[go];
        }
        *(uint4*)&sQh[r * KP + c8] = vh;
    }
    __syncthreads();

    const int wm = wid & 1;
    const int wn = wid >> 1;

    for (int qt = 0; qt < 7; qt++) {
        const int q0 = qt * 32;

        // ---- scores ----
        {
            float acc[7][4];
#pragma unroll
            for (int nt = 0; nt < 7; nt++)
#pragma unroll
                for (int e = 0; e < 4; e++) acc[nt][e] = 0.0f;

#pragma unroll
            for (int ks = 0; ks < 4; ks++) {
                uint32_t qf[4];
                const int arow = wm * 16 + a_row;
                ldsm_x4(qf, smem_u32(&sQh[arow * KP + ks * 16 + a_koff]));
#pragma unroll
                for (int np = 0; np < 4; np++) {
                    const int nrow = wn * 56 + np * 16 + b_rowl;
                    uint32_t kf[4];
                    ldsm_x4(kf, smem_u32(&sKh[nrow * KP + ks * 16 + b_koff]));
#pragma unroll
                    for (int hh2 = 0; hh2 < 2; hh2++) {
                        const int nt = 2 * np + hh2;
                        if (nt < 7)
                            mma_16816(acc[nt], qf, kf[2*hh2], kf[2*hh2+1]);
                    }
                }
            }
#pragma unroll
            for (int nt = 0; nt < 7; nt++) {
                const int col = wn * 56 + nt * 8 + cc;
                const int r0  = wm * 16 + g;
                *(float2*)&sPf[r0 * PFP + col] =
                    make_float2(acc[nt][0], acc[nt][1]);
                *(float2*)&sPf[(r0 + 8) * PFP + col] =
                    make_float2(acc[nt][2], acc[nt][3]);
            }
        }
        __syncthreads();

        // ---- softmax -> fp16 probs; shadow-stage Q(qt+1) ----
        {
#pragma unroll
            for (int rr = 0; rr < 4; rr++) {
                const int row = wid * 4 + rr;
                float v[7];
#pragma unroll
                for (int t = 0; t < 7; t++) {
                    const int col = lane + t * 32;
                    v[t] = (col < SEQ) ? sPf[row * PFP + col] : -INFINITY;
                }
                float mx = v[0];
#pragma unroll
                for (int t = 1; t < 7; t++) mx = fmaxf(mx, v[t]);
#pragma unroll
                for (int o = 16; o > 0; o >>= 1)
                    mx = fmaxf(mx, __shfl_xor_sync(0xffffffffu, mx, o));
                float s = 0.0f;
#pragma unroll
                for (int t = 0; t < 7; t++) {
                    const int col = lane + t * 32;
                    float e = (col < SEQ) ? __expf((v[t] - mx) * 0.125f) : 0.0f;
                    v[t] = e;
                    s += e;
                }
#pragma unroll
                for (int o = 16; o > 0; o >>= 1)
                    s += __shfl_xor_sync(0xffffffffu, s, o);
                const float inv = 1.0f / s;
#pragma unroll
                for (int t = 0; t < 7; t++) {
                    const int col = lane + t * 32;
                    sPbh[row * VP + col] = __float2half_rn(v[t] * inv);
                }
            }
            if (qt < 6) {   // sQ idle in this phase: stage next Q tile
                int r = tid >> 3, c8 = (tid & 7) * 8;
                uint4 vh = make_uint4(0, 0, 0, 0);
                int qq = q0 + 32 + r;
                if (qq < SEQ) {
                    const size_t go = (size_t)(rbase + qq) * NQKV + qoff + c8;
                    vh = *(const uint4*)&g_qkvh[go];
                }
                *(uint4*)&sQh[r * KP + c8] = vh;
            }
        }
        __syncthreads();

        // ---- P.V ----
        {
            const int wm2 = wid & 1;
            const int wn2 = wid >> 1;
            float acc2[2][4];
#pragma unroll
            for (int nt = 0; nt < 2; nt++)
#pragma unroll
                for (int e = 0; e < 4; e++) acc2[nt][e] = 0.0f;

#pragma unroll
            for (int ks = 0; ks < 14; ks++) {
                uint32_t pf[4];
                const int arow = wm2 * 16 + a_row;
                ldsm_x4(pf, smem_u32(&sPbh[arow * VP + ks * 16 + a_koff]));
                const int nrow = wn2 * 16 + b_rowl;
                uint32_t vf[4];
                ldsm_x4(vf, smem_u32(&sVth[nrow * VP + ks * 16 + b_koff]));
#pragma unroll
                for (int hh2 = 0; hh2 < 2; hh2++)
                    mma_16816(acc2[hh2], pf, vf[2*hh2], vf[2*hh2+1]);
            }
#pragma unroll
            for (int hh2 = 0; hh2 < 2; hh2++) {
                const int col = hc + wn2 * 16 + hh2 * 8 + cc;
#pragma unroll
                for (int half = 0; half < 2; half++) {
                    const int qq = q0 + wm2 * 16 + g + half * 8;
                    if (qq < SEQ) {
                        float o0 = acc2[hh2][2 * half + 0];
                        float o1 = acc2[hh2][2 * half + 1];
                        const size_t go = (size_t)(rbase + qq) * DMODEL + col;
                        __half h0 = __float2half_rn(o0);
                        __half h1 = __float2half_rn(o1);
                        __half hv[2] = {h0, h1};
                        __half lv[2] = {
                            __float2half_rn(o0 - __half2float(h0)),
                            __float2half_rn(o1 - __half2float(h1))};
                        *(uint32_t*)&g_ch[go] = *(uint32_t*)hv;
                        *(uint32_t*)&g_cl[go] = *(uint32_t*)lv;
                    }
                }
            }
        }
    }
}

// ===========================================================================
extern "C" void kernel_launch(void* const* d_in, const int* in_sizes, int n_in,
                              void* d_out, int out_size)
{
    const float* hidden = (const float*)d_in[0];
    const float* Wq = (const float*)d_in[1];
    const float* bq = (const float*)d_in[2];
    const float* Wk = (const float*)d_in[3];
    const float* bk = (const float*)d_in[4];
    const float* Wv = (const float*)d_in[5];
    const float* bv = (const float*)d_in[6];
    const float* Wd = (const float*)d_in[7];
    const float* bd = (const float*)d_in[8];
    const float* W1 = (const float*)d_in[9];
    const float* b1 = (const float*)d_in[10];
    const float* W2 = (const float*)d_in[11];
    const float* b2 = (const float*)d_in[12];
    float* out = (float*)d_out;

    unsigned char* mask;
    __half *hh, *ch, *cl, *qkvh, *wfuse, *wdh, *vt;
    float *bfuse;
    cudaGetSymbolAddress((void**)&bfuse, g_bfuse);
    cudaGetSymbolAddress((void**)&mask,  g_mask);
    cudaGetSymbolAddress((void**)&hh,    g_hh);
    cudaGetSymbolAddress((void**)&ch,    g_ch);
    cudaGetSymbolAddress((void**)&cl,    g_cl);
    cudaGetSymbolAddress((void**)&qkvh,  g_qkvh);
    cudaGetSymbolAddress((void**)&vt,    g_vt);
    cudaGetSymbolAddress((void**)&wfuse, g_wfuse);
    cudaGetSymbolAddress((void**)&wdh,   g_wdh);

    const int SMG = 3 * GSTAGE * 2;   // 110592 bytes
    cudaFuncSetAttribute(mma_gemm<3>, cudaFuncAttributeMaxDynamicSharedMemorySize, SMG);
    cudaFuncSetAttribute(mma_gemm<2>, cudaFuncAttributeMaxDynamicSharedMemorySize, SMG);
    cudaFuncSetAttribute(attn_mma, cudaFuncAttributeMaxDynamicSharedMemorySize, ATT_SMEM);

    // ---- one prep launch: conversions + transposes + bias pack ----
    prep_kernel<<<NB_PREP, 256>>>(hidden, Wq, Wk, Wv, Wd, W1, bq, bk, bv, b1);

    // ---- fused QKV + h1 + mask projection (V written transposed) ----
    mma_gemm<3><<<dim3(19, 197), 128, SMG>>>(
        hh, wfuse, bfuse, nullptr, NQKV, nullptr, nullptr,
        qkvh, vt, nullptr, nullptr, W2, b2);

    // ---- attention -> ctx (fp16 hi/lo) ----
    attn_mma<<<BATCH * NHEAD, 256, ATT_SMEM>>>();

    // ---- out = mask ? ctx @ Wd + bd + ctx : hidden ----
    mma_gemm<2><<<dim3(6, 197), 128, SMG>>>(
        ch, wdh, bd, out, DMODEL, mask, hidden,
        nullptr, nullptr, ch, cl, nullptr, nullptr);
}

// round 17
// speedup vs baseline: 1.0410x; 1.0410x over previous
#include <cuda_runtime.h>
#include <cuda_fp16.h>
#include <math.h>
#include <stdint.h>

// Problem constants
#define BATCH  128
#define SEQ    197
#define DMODEL 768
#define NQKV   2304                // 3 * DMODEL (packed Q,K,V)
#define NFUSE  2432                // NQKV + 128 (h1 cols 2304..2367, pad ..2431)
#define NHEAD  12
#define DHEAD  64
#define M_TOT  (BATCH * SEQ)       // 25216 = 197 * 128
#define SPAD   224                 // padded key count (7 x 32)

// -------------------- scratch (__device__ globals; no allocs allowed) ------
__device__ unsigned char g_mask[M_TOT];
__device__ float g_bfuse[NFUSE];

// fp16 operands (single-pass fp16; fp32 accumulate in MMA)
__device__ __half g_hh[M_TOT * DMODEL];                        // hidden
__device__ __half g_ch[M_TOT * DMODEL], g_cl[M_TOT * DMODEL];  // ctx hi/lo
__device__ __half g_qkvh[(size_t)M_TOT * NQKV];                // packed Q,K (V region unused)
// V transposed: [(b*12+h)*64 + d][224 keys], zero-init padding keys>=197
__device__ __half g_vt[(size_t)BATCH * NHEAD * DHEAD * SPAD];

// packed [Wqkv | W1pad]^T [2432, 768] ; Wd^T
__device__ __half g_wfuse[(size_t)NFUSE * DMODEL];
__device__ __half g_wdh[DMODEL * DMODEL];

// ======================= warp MMA helpers (arch-neutral PTX) ===============
__device__ __forceinline__ uint32_t smem_u32(const void* p) {
    uint32_t a;
    asm("{ .reg .u64 t; cvta.to.shared.u64 t, %1; cvt.u32.u64 %0, t; }"
        : "=r"(a) : "l"(p));
    return a;
}

__device__ __forceinline__ void ldsm_x4(uint32_t r[4], uint32_t addr) {
    asm volatile("ldmatrix.sync.aligned.m8n8.x4.shared.b16 {%0,%1,%2,%3}, [%4];"
                 : "=r"(r[0]), "=r"(r[1]), "=r"(r[2]), "=r"(r[3]) : "r"(addr));
}

__device__ __forceinline__ void mma_16816(float d[4],
                                          const uint32_t a[4],
                                          const uint32_t b0, const uint32_t b1) {
    asm volatile(
        "mma.sync.aligned.m16n8k16.row.col.f32.f16.f16.f32 "
        "{%0,%1,%2,%3}, {%4,%5,%6,%7}, {%8,%9}, {%0,%1,%2,%3};"
        : "+f"(d[0]), "+f"(d[1]), "+f"(d[2]), "+f"(d[3])
        : "r"(a[0]), "r"(a[1]), "r"(a[2]), "r"(a[3]), "r"(b0), "r"(b1));
}

__device__ __forceinline__ void cp16(uint32_t saddr, const void* g) {
    asm volatile("cp.async.cg.shared.global [%0], [%1], 16;"
                 :: "r"(saddr), "l"(g) : "memory");
}

// streaming (evict-first) stores for write-once buffers
__device__ __forceinline__ void stcs_u32(void* p, uint32_t v) {
    asm volatile("st.global.cs.u32 [%0], %1;" :: "l"(p), "r"(v) : "memory");
}
__device__ __forceinline__ void stcs_u16(void* p, uint16_t v) {
    asm volatile("st.global.cs.u16 [%0], %1;" :: "l"(p), "h"(v) : "memory");
}

// ===========================================================================
// fp16 single-pass GEMM, BK=64, 3-stage cp.async, ONE barrier per k-chunk,
// 256 threads, 8 warps 4x2, warp tile 32x64, flat 16-step frag pipeline.
// EPI 2: mask ? acc+bias+(resid hi+lo) : fallback -> fp32
// EPI 3: col<1536      -> fp16 packed Q/K (st.cs, ld NQKV)
//        col<NQKV      -> fp16 V transposed into Vt[(b,h),d,s] (st.cs)
//        col<NQKV+64   -> h1 = relu(acc+bias); fused mask dot with W2
//        else          -> discard (zero pad)
// ===========================================================================
#define GSROW 72   // smem row pitch in halves (144 B = 9 x 16B, odd -> conflict-free)
#define GBN  128
#define GSTAGE ((128 + GBN) * GSROW)   // halves per stage: 18432

__device__ __forceinline__ void stage_load(
    __half* st, int tid, int bm, int bn, int k0,
    const __half* A, const __half* B)
{
    __half* pA = st;
    __half* pB = st + 128 * GSROW;
#pragma unroll
    for (int i = 0; i < 4; i++) {
        int idx = tid + i * 256;
        int r = idx >> 3, c = idx & 7;
        const size_t go = (size_t)(bm + r) * DMODEL + k0 + c * 8;
        cp16(smem_u32(&pA[r * GSROW + c * 8]), A + go);
    }
#pragma unroll
    for (int i = 0; i < 4; i++) {
        int idx = tid + i * 256;
        int r = idx >> 3, c = idx & 7;
        const size_t go = (size_t)(bn + r) * DMODEL + k0 + c * 8;
        cp16(smem_u32(&pB[r * GSROW + c * 8]), B + go);
    }
    asm volatile("cp.async.commit_group;" ::: "memory");
}

template <int EPI>
__global__ __launch_bounds__(256, 2) void mma_gemm(
    const __half* __restrict__ A, const __half* __restrict__ B,
    const float* __restrict__ bias, float* __restrict__ C, int ldo,
    const unsigned char* __restrict__ mask,
    const float* __restrict__ fallback,
    __half* __restrict__ Chh, __half* __restrict__ Vt,
    const __half* __restrict__ Rh, const __half* __restrict__ Rl,
    const float* __restrict__ W2, const float* __restrict__ b2)
{
    extern __shared__ __half dynsmem[];

    const int tid  = threadIdx.x;
    const int wid  = tid >> 5;
    const int lane = tid & 31;
    const int wm   = wid & 3;
    const int wn   = wid >> 2;
    const int bm   = blockIdx.y * 128;
    const int bn   = blockIdx.x * GBN;

    float acc[2][8][4];
#pragma unroll
    for (int mt = 0; mt < 2; mt++)
#pragma unroll
        for (int nt = 0; nt < 8; nt++)
#pragma unroll
            for (int e = 0; e < 4; e++) acc[mt][nt][e] = 0.0f;

    const int a_row  = (lane & 15);
    const int a_koff = (lane >> 4) * 8;
    const int b_rowl = ((lane >> 4) & 1) * 8 + (lane & 7);
    const int b_koff = ((lane >> 3) & 1) * 8;

    const uint32_t smbase = smem_u32(dynsmem);

    stage_load(dynsmem,          tid, bm, bn,  0, A, B);
    stage_load(dynsmem + GSTAGE, tid, bm, bn, 64, A, B);

    for (int kc = 0; kc < 12; kc++) {
        if (kc < 11) {
            asm volatile("cp.async.wait_group 1;" ::: "memory");
        } else {
            asm volatile("cp.async.wait_group 0;" ::: "memory");
        }
        __syncthreads();
        if (kc < 10) {
            stage_load(dynsmem + ((kc + 2) % 3) * GSTAGE, tid, bm, bn,
                       (kc + 2) * 64, A, B);
        }

        const uint32_t sA = smbase + (uint32_t)((kc % 3) * GSTAGE) * 2u;
        const uint32_t sB = sA + 128 * GSROW * 2u;

        // ---- 16-step flat pipeline with double-buffered fragments ----
        uint32_t aa[2][2][4];   // [ks parity][mt]
        uint32_t bb[2][4];      // [step parity]

#pragma unroll
        for (int mt = 0; mt < 2; mt++)
            ldsm_x4(aa[0][mt],
                    sA + (uint32_t)((wm * 32 + mt * 16 + a_row) * GSROW + a_koff) * 2u);
        ldsm_x4(bb[0],
                sB + (uint32_t)((wn * 64 + b_rowl) * GSROW + b_koff) * 2u);

#pragma unroll
        for (int step = 0; step < 16; step++) {
            const int ks  = step >> 2;
            const int np  = step & 3;
            const int cur = step & 1;
            if (step < 15) {
                const int nks = (step + 1) >> 2;
                const int nnp = (step + 1) & 3;
                ldsm_x4(bb[cur ^ 1],
                        sB + (uint32_t)((wn * 64 + nnp * 16 + b_rowl) * GSROW
                                        + nks * 16 + b_koff) * 2u);
                if (nnp == 0) {
#pragma unroll
                    for (int mt = 0; mt < 2; mt++)
                        ldsm_x4(aa[nks & 1][mt],
                                sA + (uint32_t)((wm * 32 + mt * 16 + a_row) * GSROW
                                                + nks * 16 + a_koff) * 2u);
                }
            }
#pragma unroll
            for (int h = 0; h < 2; h++) {
                const int nt = 2 * np + h;
#pragma unroll
                for (int mt = 0; mt < 2; mt++)
                    mma_16816(acc[mt][nt], aa[ks & 1][mt],
                              bb[cur][2 * h], bb[cur][2 * h + 1]);
            }
        }
    }

    // ---- epilogue ----
    const int g  = lane >> 2;
    const int cc = (lane & 3) * 2;
#pragma unroll
    for (int mt = 0; mt < 2; mt++) {
#pragma unroll
        for (int half = 0; half < 2; half++) {
            const int row = bm + wm * 32 + mt * 16 + g + half * 8;
            const bool mk = (EPI == 2) ? (mask[row] != 0) : false;
            const int bb2 = row / SEQ;             // used by EPI 3 V path
            const int ss = row - bb2 * SEQ;
            float mdot = 0.0f;                      // fused mask dot (EPI 3)
#pragma unroll
            for (int nt = 0; nt < 8; nt++) {
                const int col = bn + wn * 64 + nt * 8 + cc;
                float o0 = acc[mt][nt][2 * half + 0] + bias[col];
                float o1 = acc[mt][nt][2 * half + 1] + bias[col + 1];
                if (EPI == 3) {
                    if (col < 1536) {
                        const size_t go = (size_t)row * NQKV + col;
                        __half hv[2] = {__float2half_rn(o0), __float2half_rn(o1)};
                        stcs_u32(Chh + go, *(uint32_t*)hv);
                    } else if (col < NQKV) {
                        const int which = col - 1536;
                        const int hh = which >> 6;
                        const int d  = which & 63;
                        __half* vp = Vt + ((size_t)(bb2 * NHEAD + hh) * DHEAD + d)
                                          * SPAD + ss;
                        __half v0 = __float2half_rn(o0);
                        __half v1 = __float2half_rn(o1);
                        stcs_u16(vp,        *(uint16_t*)&v0);
                        stcs_u16(vp + SPAD, *(uint16_t*)&v1);   // d+1 row
                    } else if (col < NQKV + 64) {
                        const int hcol = col - NQKV;
                        mdot += fmaxf(o0, 0.0f) * W2[hcol]
                              + fmaxf(o1, 0.0f) * W2[hcol + 1];
                    }
                } else {  // EPI == 2
                    const size_t go = (size_t)row * ldo + col;
                    float* cp = C + go;
                    if (mk) {
                        float r0f = __half2float(Rh[go]) + __half2float(Rl[go]);
                        float r1f = __half2float(Rh[go + 1]) + __half2float(Rl[go + 1]);
                        *(float2*)cp = make_float2(o0 + r0f, o1 + r1f);
                    } else {
                        const float* fb = fallback + go;
                        *(float2*)cp = make_float2(fb[0], fb[1]);
                    }
                }
            }
            if (EPI == 3 && (bn + wn * 64) == NQKV) {
                // quad reduction: lanes {x, x^1, x^2, x^3} share this row
                mdot += __shfl_xor_sync(0xffffffffu, mdot, 1);
                mdot += __shfl_xor_sync(0xffffffffu, mdot, 2);
                if ((lane & 3) == 0) {
                    float p = 1.0f / (1.0f + __expf(-(mdot + b2[0])));
                    g_mask[row] = (unsigned char)((ss == 0) || (p >= 0.05f));
                }
            }
        }
    }
}

// ===========================================================================
// ONE prep kernel: half_convert | transpose_qkv | transpose W1 | w1 pad |
//                  transpose Wd | pack bias   (blockIdx.x range dispatch)
// ===========================================================================
#define NB_HC   (M_TOT * DMODEL / 4 / 256)   // 18912
#define NB_TQKV 1728
#define NB_TW1  48
#define NB_PAD  24
#define NB_TWD  576
#define NB_BIAS 10
#define NB_PREP (NB_HC + NB_TQKV + NB_TW1 + NB_PAD + NB_TWD + NB_BIAS)

__global__ __launch_bounds__(256) void prep_kernel(
    const float* __restrict__ hidden,
    const float* __restrict__ Wq, const float* __restrict__ Wk,
    const float* __restrict__ Wv, const float* __restrict__ Wd,
    const float* __restrict__ W1,
    const float* __restrict__ bq, const float* __restrict__ bk,
    const float* __restrict__ bv, const float* __restrict__ b1)
{
    __shared__ float t[32][33];
    const int tid = threadIdx.x;
    int bid = blockIdx.x;

    if (bid < NB_HC) {
        int i = bid * 256 + tid;
        float4 x = *(const float4*)(hidden + (size_t)i * 4);
        __half hv[4] = {__float2half_rn(x.x), __float2half_rn(x.y),
                        __float2half_rn(x.z), __float2half_rn(x.w)};
        *(uint2*)(g_hh + (size_t)i * 4) = *(uint2*)hv;
        return;
    }
    bid -= NB_HC;
    if (bid < NB_TQKV) {
        const int k0 = (bid % 24) * 32;
        const int yy = bid / 24;
        const int which = yy / 24;
        const int n0 = (yy % 24) * 32;
        const float* W = (which == 0) ? Wq : (which == 1) ? Wk : Wv;
        const int tx = tid & 31, ty = tid >> 5;
#pragma unroll
        for (int i = 0; i < 32; i += 8)
            t[ty + i][tx] = W[(size_t)(k0 + ty + i) * DMODEL + n0 + tx];
        __syncthreads();
#pragma unroll
        for (int i = 0; i < 32; i += 8)
            g_wfuse[(size_t)(which * DMODEL + n0 + ty + i) * DMODEL + k0 + tx] =
                __float2half_rn(t[tx][ty + i]);
        return;
    }
    bid -= NB_TQKV;
    if (bid < NB_TW1) {
        const int k0 = (bid % 24) * 32;
        const int n0 = (bid / 24) * 32;
        const int tx = tid & 31, ty = tid >> 5;
#pragma unroll
        for (int i = 0; i < 32; i += 8)
            t[ty + i][tx] = W1[(size_t)(k0 + ty + i) * 64 + n0 + tx];
        __syncthreads();
#pragma unroll
        for (int i = 0; i < 32; i += 8)
            g_wfuse[(size_t)(NQKV + n0 + ty + i) * DMODEL + k0 + tx] =
                __float2half_rn(t[tx][ty + i]);
        return;
    }
    bid -= NB_TW1;
    if (bid < NB_PAD) {
        int i = bid * 256 + tid;
        if (i < 6144)
            ((uint4*)(g_wfuse + (size_t)(NQKV + 64) * DMODEL))[i] =
                make_uint4(0, 0, 0, 0);
        return;
    }
    bid -= NB_PAD;
    if (bid < NB_TWD) {
        const int k0 = (bid % 24) * 32;
        const int n0 = (bid / 24) * 32;
        const int tx = tid & 31, ty = tid >> 5;
#pragma unroll
        for (int i = 0; i < 32; i += 8)
            t[ty + i][tx] = Wd[(size_t)(k0 + ty + i) * DMODEL + n0 + tx];
        __syncthreads();
#pragma unroll
        for (int i = 0; i < 32; i += 8)
            g_wdh[(size_t)(n0 + ty + i) * DMODEL + k0 + tx] =
                __float2half_rn(t[tx][ty + i]);
        return;
    }
    bid -= NB_TWD;
    {
        int i = bid * 256 + tid;
        if (i < NFUSE) {
            float v;
            if      (i < 768)  v = bq[i];
            else if (i < 1536) v = bk[i - 768];
            else if (i < 2304) v = bv[i - 1536];
            else if (i < 2368) v = b1[i - 2304];
            else               v = 0.0f;
            g_bfuse[i] = v;
        }
    }
}

// ===========================================================================
// MMA attention: one CTA per (b, h). V staged from pre-transposed g_vt.
// Streaming (__ldcs) global reads: qkv/vt are read exactly once.
// ===========================================================================
#define KP   72      // K/Q smem pitch (halves)
#define VP   232     // Vt / P pitch (halves)
#define PFP  228     // P fp32 pitch (floats)

#define OFF_KH  0
#define OFF_VTH (OFF_KH + 232 * KP * 2)          // 33408
#define OFF_QH  (OFF_VTH + 64 * VP * 2)          // 63104
#define OFF_PF  (OFF_QH + 32 * KP * 2)           // 67712
#define OFF_PBH (OFF_PF + 32 * PFP * 4)          // 96896
#define ATT_SMEM (OFF_PBH + 32 * VP * 2)         // 111744

__global__ __launch_bounds__(256, 2) void attn_mma()
{
    extern __shared__ char sm[];
    __half* sKh  = (__half*)(sm + OFF_KH);
    __half* sVth = (__half*)(sm + OFF_VTH);
    __half* sQh  = (__half*)(sm + OFF_QH);
    float*  sPf  = (float*)(sm + OFF_PF);
    __half* sPbh = (__half*)(sm + OFF_PBH);

    const int b   = blockIdx.x / NHEAD;
    const int h   = blockIdx.x % NHEAD;
    const int tid = threadIdx.x;
    const int wid = tid >> 5;
    const int lane = tid & 31;
    const int rbase = b * SEQ;

    const size_t qoff = (size_t)h * DHEAD;
    const size_t koff = (size_t)DMODEL + h * DHEAD;
    const int hc = h * DHEAD;
    const __half* vt = g_vt + (size_t)(b * NHEAD + h) * DHEAD * SPAD;

    const int a_row  = (lane & 15);
    const int a_koff = (lane >> 4) * 8;
    const int b_rowl = ((lane >> 4) & 1) * 8 + (lane & 7);
    const int b_koff = ((lane >> 3) & 1) * 8;
    const int g  = lane >> 2;
    const int cc = (lane & 3) * 2;

    // ---- stage K (zero-padded rows) ----
    {
        const uint4 z = make_uint4(0, 0, 0, 0);
        for (int idx = tid; idx < SPAD * 8; idx += 256) {
            int r = idx >> 3, c8 = (idx & 7) * 8;
            uint4 vh = z;
            if (r < SEQ) {
                const size_t go = (size_t)(rbase + r) * NQKV + koff + c8;
                vh = __ldcs((const uint4*)&g_qkvh[go]);
            }
            *(uint4*)&sKh[r * KP + c8] = vh;
        }
    }
    // ---- stage V transposed (uint4 from pre-transposed g_vt) ----
    {
        for (int idx = tid; idx < 64 * 28; idx += 256) {   // 1792 uint4
            int d = idx / 28, k8 = (idx % 28) * 8;
            *(uint4*)&sVth[d * VP + k8] = __ldcs((const uint4*)&vt[d * SPAD + k8]);
        }
    }
    // ---- stage Q tile 0 ----
    {
        int r = tid >> 3, c8 = (tid & 7) * 8;
        uint4 vh = make_uint4(0, 0, 0, 0);
        if (r < SEQ) {
            const size_t go = (size_t)(rbase + r) * NQKV + qoff + c8;
            vh = __ldcs((const uint4*)&g_qkvh[go]);
        }
        *(uint4*)&sQh[r * KP + c8] = vh;
    }
    __syncthreads();

    const int wm = wid & 1;
    const int wn = wid >> 1;

    for (int qt = 0; qt < 7; qt++) {
        const int q0 = qt * 32;

        // ---- scores ----
        {
            float acc[7][4];
#pragma unroll
            for (int nt = 0; nt < 7; nt++)
#pragma unroll
                for (int e = 0; e < 4; e++) acc[nt][e] = 0.0f;

#pragma unroll
            for (int ks = 0; ks < 4; ks++) {
                uint32_t qf[4];
                const int arow = wm * 16 + a_row;
                ldsm_x4(qf, smem_u32(&sQh[arow * KP + ks * 16 + a_koff]));
#pragma unroll
                for (int np = 0; np < 4; np++) {
                    const int nrow = wn * 56 + np * 16 + b_rowl;
                    uint32_t kf[4];
                    ldsm_x4(kf, smem_u32(&sKh[nrow * KP + ks * 16 + b_koff]));
#pragma unroll
                    for (int hh2 = 0; hh2 < 2; hh2++) {
                        const int nt = 2 * np + hh2;
                        if (nt < 7)
                            mma_16816(acc[nt], qf, kf[2*hh2], kf[2*hh2+1]);
                    }
                }
            }
#pragma unroll
            for (int nt = 0; nt < 7; nt++) {
                const int col = wn * 56 + nt * 8 + cc;
                const int r0  = wm * 16 + g;
                *(float2*)&sPf[r0 * PFP + col] =
                    make_float2(acc[nt][0], acc[nt][1]);
                *(float2*)&sPf[(r0 + 8) * PFP + col] =
                    make_float2(acc[nt][2], acc[nt][3]);
            }
        }
        __syncthreads();

        // ---- softmax -> fp16 probs; shadow-stage Q(qt+1) ----
        {
#pragma unroll
            for (int rr = 0; rr < 4; rr++) {
                const int row = wid * 4 + rr;
                float v[7];
#pragma unroll
                for (int t = 0; t < 7; t++) {
                    const int col = lane + t * 32;
                    v[t] = (col < SEQ) ? sPf[row * PFP + col] : -INFINITY;
                }
                float mx = v[0];
#pragma unroll
                for (int t = 1; t < 7; t++) mx = fmaxf(mx, v[t]);
#pragma unroll
                for (int o = 16; o > 0; o >>= 1)
                    mx = fmaxf(mx, __shfl_xor_sync(0xffffffffu, mx, o));
                float s = 0.0f;
#pragma unroll
                for (int t = 0; t < 7; t++) {
                    const int col = lane + t * 32;
                    float e = (col < SEQ) ? __expf((v[t] - mx) * 0.125f) : 0.0f;
                    v[t] = e;
                    s += e;
                }
#pragma unroll
                for (int o = 16; o > 0; o >>= 1)
                    s += __shfl_xor_sync(0xffffffffu, s, o);
                const float inv = 1.0f / s;
#pragma unroll
                for (int t = 0; t < 7; t++) {
                    const int col = lane + t * 32;
                    sPbh[row * VP + col] = __float2half_rn(v[t] * inv);
                }
            }
            if (qt < 6) {   // sQ idle in this phase: stage next Q tile
                int r = tid >> 3, c8 = (tid & 7) * 8;
                uint4 vh = make_uint4(0, 0, 0, 0);
                int qq = q0 + 32 + r;
                if (qq < SEQ) {
                    const size_t go = (size_t)(rbase + qq) * NQKV + qoff + c8;
                    vh = __ldcs((const uint4*)&g_qkvh[go]);
                }
                *(uint4*)&sQh[r * KP + c8] = vh;
            }
        }
        __syncthreads();

        // ---- P.V ----
        {
            const int wm2 = wid & 1;
            const int wn2 = wid >> 1;
            float acc2[2][4];
#pragma unroll
            for (int nt = 0; nt < 2; nt++)
#pragma unroll
                for (int e = 0; e < 4; e++) acc2[nt][e] = 0.0f;

#pragma unroll
            for (int ks = 0; ks < 14; ks++) {
                uint32_t pf[4];
                const int arow = wm2 * 16 + a_row;
                ldsm_x4(pf, smem_u32(&sPbh[arow * VP + ks * 16 + a_koff]));
                const int nrow = wn2 * 16 + b_rowl;
                uint32_t vf[4];
                ldsm_x4(vf, smem_u32(&sVth[nrow * VP + ks * 16 + b_koff]));
#pragma unroll
                for (int hh2 = 0; hh2 < 2; hh2++)
                    mma_16816(acc2[hh2], pf, vf[2*hh2], vf[2*hh2+1]);
            }
#pragma unroll
            for (int hh2 = 0; hh2 < 2; hh2++) {
                const int col = hc + wn2 * 16 + hh2 * 8 + cc;
#pragma unroll
                for (int half = 0; half < 2; half++) {
                    const int qq = q0 + wm2 * 16 + g + half * 8;
                    if (qq < SEQ) {
                        float o0 = acc2[hh2][2 * half + 0];
                        float o1 = acc2[hh2][2 * half + 1];
                        const size_t go = (size_t)(rbase + qq) * DMODEL + col;
                        __half h0 = __float2half_rn(o0);
                        __half h1 = __float2half_rn(o1);
                        __half hv[2] = {h0, h1};
                        __half lv[2] = {
                            __float2half_rn(o0 - __half2float(h0)),
                            __float2half_rn(o1 - __half2float(h1))};
                        *(uint32_t*)&g_ch[go] = *(uint32_t*)hv;
                        *(uint32_t*)&g_cl[go] = *(uint32_t*)lv;
                    }
                }
            }
        }
    }
}

// ===========================================================================
extern "C" void kernel_launch(void* const* d_in, const int* in_sizes, int n_in,
                              void* d_out, int out_size)
{
    const float* hidden = (const float*)d_in[0];
    const float* Wq = (const float*)d_in[1];
    const float* bq = (const float*)d_in[2];
    const float* Wk = (const float*)d_in[3];
    const float* bk = (const float*)d_in[4];
    const float* Wv = (const float*)d_in[5];
    const float* bv = (const float*)d_in[6];
    const float* Wd = (const float*)d_in[7];
    const float* bd = (const float*)d_in[8];
    const float* W1 = (const float*)d_in[9];
    const float* b1 = (const float*)d_in[10];
    const float* W2 = (const float*)d_in[11];
    const float* b2 = (const float*)d_in[12];
    float* out = (float*)d_out;

    unsigned char* mask;
    __half *hh, *ch, *cl, *qkvh, *wfuse, *wdh, *vt;
    float *bfuse;
    cudaGetSymbolAddress((void**)&bfuse, g_bfuse);
    cudaGetSymbolAddress((void**)&mask,  g_mask);
    cudaGetSymbolAddress((void**)&hh,    g_hh);
    cudaGetSymbolAddress((void**)&ch,    g_ch);
    cudaGetSymbolAddress((void**)&cl,    g_cl);
    cudaGetSymbolAddress((void**)&qkvh,  g_qkvh);
    cudaGetSymbolAddress((void**)&vt,    g_vt);
    cudaGetSymbolAddress((void**)&wfuse, g_wfuse);
    cudaGetSymbolAddress((void**)&wdh,   g_wdh);

    const int SMG = 3 * GSTAGE * 2;   // 110592 bytes
    cudaFuncSetAttribute(mma_gemm<3>, cudaFuncAttributeMaxDynamicSharedMemorySize, SMG);
    cudaFuncSetAttribute(mma_gemm<2>, cudaFuncAttributeMaxDynamicSharedMemorySize, SMG);
    cudaFuncSetAttribute(attn_mma, cudaFuncAttributeMaxDynamicSharedMemorySize, ATT_SMEM);

    // ---- one prep launch: conversions + transposes + bias pack ----
    prep_kernel<<<NB_PREP, 256>>>(hidden, Wq, Wk, Wv, Wd, W1, bq, bk, bv, b1);

    // ---- fused QKV + h1 + mask projection (V written transposed) ----
    mma_gemm<3><<<dim3(19, 197), 256, SMG>>>(
        hh, wfuse, bfuse, nullptr, NQKV, nullptr, nullptr,
        qkvh, vt, nullptr, nullptr, W2, b2);

    // ---- attention -> ctx (fp16 hi/lo) ----
    attn_mma<<<BATCH * NHEAD, 256, ATT_SMEM>>>();

    // ---- out = mask ? ctx @ Wd + bd + ctx : hidden ----
    mma_gemm<2><<<dim3(6, 197), 256, SMG>>>(
        ch, wdh, bd, out, DMODEL, mask, hidden,
        nullptr, nullptr, ch, cl, nullptr, nullptr);
}